// round 3
// baseline (speedup 1.0000x reference)
#include <cuda_runtime.h>
#include <cstdint>

#define SEQ 16384
#define EMBD 50
#define HID 300
#define G4 1200
#define NTAG 20
#define START_TAG 18
#define STOP_TAG 19
#define NEGV -10000.0f

// ---------------- scratch (static device globals; no allocation) ----------------
__device__ float d_xg[2][SEQ][G4];                     // input projections (bwd stored time-reversed)
__device__ float d_hout[2][SEQ][HID];                  // hf[s], hb[s] (bwd stored un-reversed)
__device__ __align__(16) float d_feats[SEQ][NTAG];
__device__ __align__(16) unsigned char d_bp[SEQ * NTAG];
__device__ int d_best;

// ---------------- kernel 1: embedding + input projection ----------------
__global__ void k_embed_proj(const int* __restrict__ sent, const float* __restrict__ embed,
                             const float* __restrict__ wf, const float* __restrict__ bfi,
                             const float* __restrict__ bfh,
                             const float* __restrict__ wb, const float* __restrict__ bbi,
                             const float* __restrict__ bbh)
{
    int s = blockIdx.x;
    __shared__ float e[EMBD];
    int tok = sent[s];
    for (int k = threadIdx.x; k < EMBD; k += blockDim.x)
        e[k] = embed[(size_t)tok * EMBD + k];
    __syncthreads();
    for (int j = threadIdx.x; j < 2 * G4; j += blockDim.x) {
        bool isF = j < G4;
        int jj = isF ? j : j - G4;
        const float* w = (isF ? wf : wb) + (size_t)jj * EMBD;
        float acc = isF ? (bfi[jj] + bfh[jj]) : (bbi[jj] + bbh[jj]);
#pragma unroll
        for (int k = 0; k < EMBD; k++) acc = fmaf(e[k], __ldg(&w[k]), acc);
        if (isF) d_xg[0][s][jj] = acc;
        else     d_xg[1][SEQ - 1 - s][jj] = acc;   // bwd step t consumes emb[SEQ-1-t]
    }
}

// ---------------- kernel 2: cluster-cooperative LSTM recurrence ----------------
__device__ __forceinline__ float sigm(float x) { return 1.0f / (1.0f + expf(-x)); }

#define CELLS_PER 38
#define ROWS_PER 152          // 4 gates * 38 cells
#define NCHUNK 6
#define KC 50                 // 6*50 = 300 = HID
#define HPAD 304
#define SMEM_W (ROWS_PER * HID)                                        // 45600 floats
#define SMEM_FLOATS (SMEM_W + 2 * HPAD + ROWS_PER * NCHUNK + ROWS_PER + CELLS_PER)
#define LSTM_SMEM_BYTES (SMEM_FLOATS * 4)

__global__ void k_lstm(const float* __restrict__ whh_f, const float* __restrict__ whh_b,
                       const float* __restrict__ h0, const float* __restrict__ c0in)
{
    extern __shared__ float sm[];
    float* w_s   = sm;                       // [152][300] weight slice (cell-gate interleaved rows)
    float* h_s   = sm + SMEM_W;              // [2][304] double-buffered hidden state
    float* pacc  = h_s + 2 * HPAD;           // [152][6] matvec partials
    float* gates = pacc + ROWS_PER * NCHUNK; // [152]
    float* c_s   = gates + ROWS_PER;         // [38]

    int tid  = threadIdx.x;
    int rank = blockIdx.x & 7;       // cluster rank (clusters are contiguous 8-block groups)
    int dir  = blockIdx.x >> 3;     // cluster 0 = forward, cluster 1 = backward
    int cbase = rank * CELLS_PER;    // rank 7 owns only 34 valid cells (300 = 7*38 + 34)
    const float* whh = dir ? whh_b : whh_f;
    const float* xg  = &d_xg[dir][0][0];

    // Load weight slice; zero-pad rows of invalid cells so matvec needs no bounds checks.
    for (int idx = tid; idx < ROWS_PER * HID; idx += blockDim.x) {
        int row = idx / HID, k = idx - row * HID;
        int cell = row >> 2, gate = row & 3;
        int gc = cbase + cell;
        w_s[row * HID + k] = (gc < HID) ? whh[((size_t)(gate * HID + gc)) * HID + k] : 0.0f;
    }
    for (int k = tid; k < 2 * HPAD; k += blockDim.x) {
        int kk = k % HPAD;
        h_s[k] = (kk < HID) ? h0[dir * HID + kk] : 0.0f;   // init both buffers (buffer 0 used at t=0)
    }
    if (tid < CELLS_PER) {
        int gc = cbase + tid;
        c_s[tid] = (gc < HID) ? c0in[dir * HID + gc] : 0.0f;
    }
    __syncthreads();
    // all CTAs must have h_s initialized before anyone's step-0 remote stores land
    asm volatile("barrier.cluster.arrive.aligned;" ::: "memory");
    asm volatile("barrier.cluster.wait.aligned;" ::: "memory");

    uint32_t h_smem_base = (uint32_t)__cvta_generic_to_shared(h_s);

    for (int t = 0; t < SEQ; t++) {
        // prefetch this thread's xg element (latency hidden under the matvec)
        float xval = 0.0f;
        if (tid < ROWS_PER) {
            int cell = tid >> 2, gate = tid & 3, gc = cbase + cell;
            if (gc < HID) xval = __ldg(&xg[(size_t)t * G4 + gate * HID + gc]);
        }
        // matvec partials: thread = (cell, k-chunk), covers 4 gate rows x 50 k
        if (tid < CELLS_PER * NCHUNK) {
            int cell = tid / NCHUNK, chunk = tid - cell * NCHUNK;
            int k0 = chunk * KC;
            const float* hb = h_s + (t & 1) * HPAD + k0;
            const float* w0 = w_s + (cell * 4) * HID + k0;
            float a0 = 0, a1 = 0, a2 = 0, a3 = 0;
#pragma unroll
            for (int k = 0; k < KC; k++) {
                float hv = hb[k];
                a0 = fmaf(w0[k],           hv, a0);
                a1 = fmaf(w0[HID + k],     hv, a1);
                a2 = fmaf(w0[2 * HID + k], hv, a2);
                a3 = fmaf(w0[3 * HID + k], hv, a3);
            }
            int pb = (cell * 4) * NCHUNK + chunk;
            pacc[pb]              = a0;
            pacc[pb + NCHUNK]     = a1;
            pacc[pb + 2 * NCHUNK] = a2;
            pacc[pb + 3 * NCHUNK] = a3;
        }
        __syncthreads();
        // reduce chunk partials + add input projection
        if (tid < ROWS_PER) {
            float sv = xval;
#pragma unroll
            for (int ch = 0; ch < NCHUNK; ch++) sv += pacc[tid * NCHUNK + ch];
            gates[tid] = sv;
        }
        __syncthreads();
        // per-cell nonlinearity + state update + broadcast h to all 8 cluster CTAs
        if (tid < CELLS_PER && cbase + tid < HID) {
            int cell = tid;
            float gi = gates[cell * 4 + 0];
            float gf = gates[cell * 4 + 1];
            float gg = gates[cell * 4 + 2];
            float go = gates[cell * 4 + 3];
            float iv = sigm(gi), fv = sigm(gf), gv = tanhf(gg), ov = sigm(go);
            float cc = fv * c_s[cell] + iv * gv;
            c_s[cell] = cc;
            float hv = ov * tanhf(cc);
            int pos = dir ? (SEQ - 1 - t) : t;
            d_hout[dir][pos][cbase + cell] = hv;
            uint32_t dst = h_smem_base + (uint32_t)((((t + 1) & 1) * HPAD + cbase + cell) * 4);
#pragma unroll
            for (int p = 0; p < 8; p++) {
                uint32_t ra;
                asm volatile("mapa.shared::cluster.u32 %0, %1, %2;" : "=r"(ra) : "r"(dst), "r"(p));
                asm volatile("st.shared::cluster.f32 [%0], %1;" :: "r"(ra), "f"(hv));
            }
        }
        // release our h writes / acquire peers' writes
        asm volatile("barrier.cluster.arrive.aligned;" ::: "memory");
        asm volatile("barrier.cluster.wait.aligned;" ::: "memory");
    }
}

// ---------------- kernel 3: tag projection (feats) ----------------
__global__ void k_feats(const float* __restrict__ wtag, const float* __restrict__ btag)
{
    int s = blockIdx.x;
    __shared__ float hbuf[2 * HID];
    int tid = threadIdx.x;
    for (int i = tid; i < 2 * HID; i += blockDim.x)
        hbuf[i] = (i < HID) ? d_hout[0][s][i] : d_hout[1][s][i - HID];
    __syncthreads();
    int warp = tid >> 5, lane = tid & 31;
    if (warp < NTAG) {
        const float* w = wtag + warp * 2 * HID;
        float acc = 0;
        for (int k = lane; k < 2 * HID; k += 32)
            acc = fmaf(hbuf[k], __ldg(&w[k]), acc);
#pragma unroll
        for (int off = 16; off; off >>= 1) acc += __shfl_down_sync(0xffffffffu, acc, off);
        if (lane == 0) d_feats[s][warp] = acc + btag[warp];
    }
}

// ---------------- kernel 4: Viterbi forward ----------------
#define VCH 512
#define VIT_SMEM_BYTES (2 * VCH * NTAG * 4)
__global__ void k_viterbi(const float* __restrict__ trans, float* out, int out_size)
{
    extern __shared__ float fb[];   // [2][VCH*NTAG] staged feats
    int tid = threadIdx.x;
    int lane = tid & 31;

    if (tid >= 32) {   // preload chunk 0
        const float4* src = (const float4*)&d_feats[0][0];
        float4* dst = (float4*)fb;
        for (int i = tid - 32; i < VCH * NTAG / 4; i += (int)blockDim.x - 32) dst[i] = src[i];
    }
    __syncthreads();

    float fv = NEGV;
    float trow[NTAG];
    if (tid < 32) {
        if (lane < NTAG) {
            fv = (lane == START_TAG) ? 0.0f : NEGV;
#pragma unroll
            for (int p = 0; p < NTAG; p++) trow[p] = __ldg(&trans[lane * NTAG + p]);
        } else {
#pragma unroll
            for (int p = 0; p < NTAG; p++) trow[p] = 0.0f;
        }
    }

    const int nch = SEQ / VCH;
    for (int c = 0; c < nch; c++) {
        if (tid >= 32) {
            if (c + 1 < nch) {
                const float4* src = (const float4*)&d_feats[(c + 1) * VCH][0];
                float4* dst = (float4*)(fb + ((c + 1) & 1) * VCH * NTAG);
                for (int i = tid - 32; i < VCH * NTAG / 4; i += (int)blockDim.x - 32) dst[i] = src[i];
            }
        } else {
            const float* fbase = fb + (c & 1) * VCH * NTAG;
            for (int j = 0; j < VCH; j++) {
                int t = c * VCH + j;
                float best = -3.4e38f; int bi = 0;
#pragma unroll
                for (int p = 0; p < NTAG; p++) {
                    float v = __shfl_sync(0xffffffffu, fv, p) + trow[p];
                    if (v > best) { best = v; bi = p; }   // strict > == first-max (jnp.argmax)
                }
                if (lane < NTAG) {
                    d_bp[t * NTAG + lane] = (unsigned char)bi;
                    fv = best + fbase[j * NTAG + lane];
                }
            }
        }
        __syncthreads();
    }

    if (tid < 32) {
        float term = (lane < NTAG) ? (fv + __ldg(&trans[STOP_TAG * NTAG + lane])) : -3.4e38f;
        float best = -3.4e38f; int bi = 0;
#pragma unroll
        for (int p = 0; p < NTAG; p++) {
            float v = __shfl_sync(0xffffffffu, term, p);
            if (v > best) { best = v; bi = p; }
        }
        if (lane == 0) {
            d_best = bi;
            if (out_size > SEQ) out[0] = best;   // score at out[0] when layout has room
        }
    }
}

// ---------------- kernel 5: backtrace ----------------
#define BCH 1024
__global__ void k_backtrace(float* out, int out_size)
{
    __shared__ unsigned char bb[2][BCH * NTAG];
    int tid = threadIdx.x;
    const int nch = SEQ / BCH;
    if (tid >= 32) {   // preload last chunk
        const uint4* src = (const uint4*)&d_bp[(size_t)(nch - 1) * BCH * NTAG];
        uint4* dst = (uint4*)bb[(nch - 1) & 1];
        for (int i = tid - 32; i < BCH * NTAG / 16; i += (int)blockDim.x - 32) dst[i] = src[i];
    }
    __syncthreads();
    int off = (out_size > SEQ) ? (out_size - SEQ) : 0;
    int tag = d_best;
    for (int c = nch - 1; c >= 0; c--) {
        if (tid >= 32) {
            if (c > 0) {
                const uint4* src = (const uint4*)&d_bp[(size_t)(c - 1) * BCH * NTAG];
                uint4* dst = (uint4*)bb[(c - 1) & 1];
                for (int i = tid - 32; i < BCH * NTAG / 16; i += (int)blockDim.x - 32) dst[i] = src[i];
            }
        } else if (tid == 0) {
            const unsigned char* b = bb[c & 1];
            for (int j = BCH - 1; j >= 0; j--) {
                int s = c * BCH + j;
                out[off + s] = (float)tag;     // y[s] = tag entering step s's backpointer
                tag = b[j * NTAG + tag];       // carry = bp[s][tag]
            }
        }
        __syncthreads();
    }
}

// ---------------- launch ----------------
extern "C" void kernel_launch(void* const* d_in, const int* in_sizes, int n_in,
                              void* d_out, int out_size)
{
    const int*   sent  = (const int*)d_in[0];
    const float* embed = (const float*)d_in[1];
    const float* wihf  = (const float*)d_in[2];
    const float* whhf  = (const float*)d_in[3];
    const float* bihf  = (const float*)d_in[4];
    const float* bhhf  = (const float*)d_in[5];
    const float* wihb  = (const float*)d_in[6];
    const float* whhb  = (const float*)d_in[7];
    const float* bihb  = (const float*)d_in[8];
    const float* bhhb  = (const float*)d_in[9];
    const float* h0    = (const float*)d_in[10];
    const float* c0    = (const float*)d_in[11];
    const float* wtag  = (const float*)d_in[12];
    const float* btag  = (const float*)d_in[13];
    const float* trans = (const float*)d_in[14];
    float* out = (float*)d_out;

    // idempotent attribute setup (host-side, no allocation, capture-safe)
    cudaFuncSetAttribute(k_lstm, cudaFuncAttributeMaxDynamicSharedMemorySize, LSTM_SMEM_BYTES);
    cudaFuncSetAttribute(k_viterbi, cudaFuncAttributeMaxDynamicSharedMemorySize, VIT_SMEM_BYTES);

    // 1) embedding + input projections
    k_embed_proj<<<SEQ, 256>>>(sent, embed, wihf, bihf, bhhf, wihb, bihb, bhhb);

    // 2) BiLSTM recurrence: 16 CTAs = 2 clusters of 8 (fwd / bwd)
    {
        cudaLaunchConfig_t cfg = {};
        cfg.gridDim = dim3(16, 1, 1);
        cfg.blockDim = dim3(256, 1, 1);
        cfg.dynamicSmemBytes = LSTM_SMEM_BYTES;
        cfg.stream = 0;
        cudaLaunchAttribute attrs[1];
        attrs[0].id = cudaLaunchAttributeClusterDimension;
        attrs[0].val.clusterDim.x = 8;
        attrs[0].val.clusterDim.y = 1;
        attrs[0].val.clusterDim.z = 1;
        cfg.attrs = attrs;
        cfg.numAttrs = 1;
        cudaLaunchKernelEx(&cfg, k_lstm, whhf, whhb, h0, c0);
    }

    // 3) tag projection
    k_feats<<<SEQ, 640>>>(wtag, btag);

    // 4) Viterbi forward (single block: 1 compute warp + 7 loader warps)
    k_viterbi<<<1, 256, VIT_SMEM_BYTES>>>(trans, out, out_size);

    // 5) backtrace
    k_backtrace<<<1, 256>>>(out, out_size);
}

// round 4
// speedup vs baseline: 1.8163x; 1.8163x over previous
#include <cuda_runtime.h>
#include <cstdint>

#define SEQ 16384
#define EMBD 50
#define HID 300
#define G4 1200
#define NTAG 20
#define START_TAG 18
#define STOP_TAG 19
#define NEGV -10000.0f

// ---------------- scratch (static device globals; no allocation) ----------------
__device__ float d_xg[2][SEQ][G4];                     // input projections (bwd stored time-reversed)
__device__ float d_hout[2][SEQ][HID];                  // hf[s], hb[s] (bwd stored un-reversed)
__device__ __align__(16) float d_feats[SEQ][NTAG];
__device__ __align__(16) unsigned char d_bp[SEQ * NTAG];
__device__ int d_best;

// ---------------- kernel 1: embedding + input projection (8 tokens/block) ----------------
#define TPB_E 256
#define TOKB 8
__global__ void k_embed_proj(const int* __restrict__ sent, const float* __restrict__ embed,
                             const float* __restrict__ wf, const float* __restrict__ bfi,
                             const float* __restrict__ bfh,
                             const float* __restrict__ wb, const float* __restrict__ bbi,
                             const float* __restrict__ bbh)
{
    int s0 = blockIdx.x * TOKB;
    __shared__ int toks[TOKB];
    __shared__ float e[TOKB][EMBD];
    int tid = threadIdx.x;
    if (tid < TOKB) toks[tid] = sent[s0 + tid];
    __syncthreads();
    for (int i = tid; i < TOKB * EMBD; i += TPB_E) {
        int u = i / EMBD, k = i - u * EMBD;
        e[u][k] = embed[(size_t)toks[u] * EMBD + k];
    }
    __syncthreads();
    for (int j = tid; j < 2 * G4; j += TPB_E) {
        bool isF = j < G4;
        int jj = isF ? j : j - G4;
        const float* w = (isF ? wf : wb) + (size_t)jj * EMBD;
        float wr[EMBD];
#pragma unroll
        for (int k = 0; k < EMBD; k++) wr[k] = __ldg(&w[k]);
        float b = isF ? (bfi[jj] + bfh[jj]) : (bbi[jj] + bbh[jj]);
#pragma unroll
        for (int u = 0; u < TOKB; u++) {
            float acc = b;
#pragma unroll
            for (int k = 0; k < EMBD; k++) acc = fmaf(e[u][k], wr[k], acc);
            int s = s0 + u;
            if (isF) d_xg[0][s][jj] = acc;
            else     d_xg[1][SEQ - 1 - s][jj] = acc;   // bwd step t consumes emb[SEQ-1-t]
        }
    }
}

// ---------------- kernel 2: cluster LSTM, register-resident weights ----------------
__device__ __forceinline__ float sigm(float x) { return 1.0f / (1.0f + expf(-x)); }

#define CELLS_PER 38
#define ROWS_PER 152          // 4 gates * 38 cells
#define KCH 100               // K-chunk per matvec thread (3 chunks = 300)
#define MV_THREADS 456        // 3 * 152
#define TPB_L 480
#define HPAD 304
#define PACCP 160

__global__ void __launch_bounds__(TPB_L, 1)
k_lstm(const float* __restrict__ whh_f, const float* __restrict__ whh_b,
       const float* __restrict__ h0, const float* __restrict__ c0in)
{
    __shared__ __align__(16) float h_s[2 * HPAD];   // double-buffered hidden state
    __shared__ float xg_s[ROWS_PER];                // this step's input projection
    __shared__ float pacc[3 * PACCP];               // matvec chunk partials

    int tid  = threadIdx.x;
    int rank = blockIdx.x & 7;       // cluster rank (contiguous 8-block clusters)
    int dir  = blockIdx.x >> 3;      // cluster 0 = forward, cluster 1 = backward
    int cbase = rank * CELLS_PER;    // rank 7 owns only 34 valid cells (300 = 7*38+34)
    const float* whh = dir ? whh_b : whh_f;
    const float* xg  = &d_xg[dir][0][0];

    // ---- matvec thread mapping: tid = chunk*152 + row (warps share chunk -> h broadcast) ----
    int chunk = tid / ROWS_PER;          // 0..2 for tid < 456
    int row   = tid - chunk * ROWS_PER;  // 0..151
    int mcell = row >> 2, mgate = row & 3;
    int mgc   = cbase + mcell;
    bool mv   = (tid < MV_THREADS) && (mgc < HID);

    // ---- weights into registers ----
    float wreg[KCH];
    {
        const float* wsrc = whh + (mv ? ((size_t)(mgate * HID + mgc) * HID + chunk * KCH) : 0);
#pragma unroll
        for (int k = 0; k < KCH; k++) wreg[k] = mv ? __ldg(&wsrc[k]) : 0.0f;
    }

    // ---- init hidden state (both buffers), cell state in register ----
    for (int k = tid; k < 2 * HPAD; k += TPB_L) {
        int kk = k % HPAD;
        h_s[k] = (kk < HID) ? h0[dir * HID + kk] : 0.0f;
    }
    float creg = 0.0f;
    if (tid < CELLS_PER && cbase + tid < HID) creg = c0in[dir * HID + cbase + tid];

    // ---- xg prefetch setup (one step ahead) ----
    bool xrow = (tid < ROWS_PER) && ((cbase + (tid >> 2)) < HID);
    size_t xoff = xrow ? (size_t)((tid & 3) * HID + cbase + (tid >> 2)) : 0;
    float xnext = xrow ? __ldg(&xg[xoff]) : 0.0f;   // xg[t=0]

    __syncthreads();
    // all CTAs finish h_s init before anyone's step-0 remote stores land
    asm volatile("barrier.cluster.arrive.aligned;" ::: "memory");
    asm volatile("barrier.cluster.wait.aligned;" ::: "memory");

    uint32_t h_smem_base = (uint32_t)__cvta_generic_to_shared(h_s);

    for (int t = 0; t < SEQ; t++) {
        // publish this step's xg (prefetched last iter); issue next prefetch
        if (tid < ROWS_PER) xg_s[tid] = xnext;
        if (xrow && t + 1 < SEQ) xnext = __ldg(&xg[(size_t)(t + 1) * G4 + xoff]);

        // matvec: weights in registers, h broadcast from SMEM via LDS.128
        if (tid < MV_THREADS) {
            const float4* hb4 = (const float4*)(h_s + (t & 1) * HPAD + chunk * KCH);
            float a0 = 0, a1 = 0, a2 = 0, a3 = 0;
#pragma unroll
            for (int i = 0; i < KCH / 4; i++) {
                float4 hv = hb4[i];
                a0 = fmaf(wreg[4 * i + 0], hv.x, a0);
                a1 = fmaf(wreg[4 * i + 1], hv.y, a1);
                a2 = fmaf(wreg[4 * i + 2], hv.z, a2);
                a3 = fmaf(wreg[4 * i + 3], hv.w, a3);
            }
            pacc[chunk * PACCP + row] = (a0 + a1) + (a2 + a3);
        }
        __syncthreads();

        // fused reduce + gate nonlinearity + state update + cluster broadcast
        if (tid < CELLS_PER) {
            int cell = tid, gc = cbase + cell;
            float g[4];
#pragma unroll
            for (int gg = 0; gg < 4; gg++) {
                int r = cell * 4 + gg;
                g[gg] = xg_s[r] + pacc[r] + pacc[PACCP + r] + pacc[2 * PACCP + r];
            }
            float iv = sigm(g[0]), fv = sigm(g[1]), gv = tanhf(g[2]), ov = sigm(g[3]);
            creg = fv * creg + iv * gv;
            float hv = ov * tanhf(creg);
            if (gc < HID) {
                int pos = dir ? (SEQ - 1 - t) : t;
                d_hout[dir][pos][gc] = hv;
                uint32_t dst = h_smem_base + (uint32_t)((((t + 1) & 1) * HPAD + gc) * 4);
#pragma unroll
                for (int p = 0; p < 8; p++) {
                    uint32_t ra;
                    asm volatile("mapa.shared::cluster.u32 %0, %1, %2;" : "=r"(ra) : "r"(dst), "r"(p));
                    asm volatile("st.shared::cluster.f32 [%0], %1;" :: "r"(ra), "f"(hv));
                }
            }
        }
        // release our h writes / acquire peers' writes (also orders xg_s/pacc reuse)
        asm volatile("barrier.cluster.arrive.aligned;" ::: "memory");
        asm volatile("barrier.cluster.wait.aligned;" ::: "memory");
    }
}

// ---------------- kernel 3: tag projection (feats) ----------------
__global__ void k_feats(const float* __restrict__ wtag, const float* __restrict__ btag)
{
    int s = blockIdx.x;
    __shared__ float hbuf[2 * HID];
    int tid = threadIdx.x;
    for (int i = tid; i < 2 * HID; i += blockDim.x)
        hbuf[i] = (i < HID) ? d_hout[0][s][i] : d_hout[1][s][i - HID];
    __syncthreads();
    int warp = tid >> 5, lane = tid & 31;
    if (warp < NTAG) {
        const float* w = wtag + warp * 2 * HID;
        float acc = 0;
        for (int k = lane; k < 2 * HID; k += 32)
            acc = fmaf(hbuf[k], __ldg(&w[k]), acc);
#pragma unroll
        for (int off = 16; off; off >>= 1) acc += __shfl_down_sync(0xffffffffu, acc, off);
        if (lane == 0) d_feats[s][warp] = acc + btag[warp];
    }
}

// ---------------- kernel 4: Viterbi forward ----------------
#define VCH 512
#define VIT_SMEM_BYTES (2 * VCH * NTAG * 4)
__global__ void k_viterbi(const float* __restrict__ trans, float* out, int out_size)
{
    extern __shared__ float fb[];   // [2][VCH*NTAG] staged feats
    int tid = threadIdx.x;
    int lane = tid & 31;

    if (tid >= 32) {   // preload chunk 0
        const float4* src = (const float4*)&d_feats[0][0];
        float4* dst = (float4*)fb;
        for (int i = tid - 32; i < VCH * NTAG / 4; i += (int)blockDim.x - 32) dst[i] = src[i];
    }
    __syncthreads();

    float fv = NEGV;
    float trow[NTAG];
    if (tid < 32) {
        if (lane < NTAG) {
            fv = (lane == START_TAG) ? 0.0f : NEGV;
#pragma unroll
            for (int p = 0; p < NTAG; p++) trow[p] = __ldg(&trans[lane * NTAG + p]);
        } else {
#pragma unroll
            for (int p = 0; p < NTAG; p++) trow[p] = 0.0f;
        }
    }

    const int nch = SEQ / VCH;
    for (int c = 0; c < nch; c++) {
        if (tid >= 32) {
            if (c + 1 < nch) {
                const float4* src = (const float4*)&d_feats[(c + 1) * VCH][0];
                float4* dst = (float4*)(fb + ((c + 1) & 1) * VCH * NTAG);
                for (int i = tid - 32; i < VCH * NTAG / 4; i += (int)blockDim.x - 32) dst[i] = src[i];
            }
        } else {
            const float* fbase = fb + (c & 1) * VCH * NTAG;
            for (int j = 0; j < VCH; j++) {
                int t = c * VCH + j;
                float best = -3.4e38f; int bi = 0;
#pragma unroll
                for (int p = 0; p < NTAG; p++) {
                    float v = __shfl_sync(0xffffffffu, fv, p) + trow[p];
                    if (v > best) { best = v; bi = p; }   // strict > == first-max (jnp.argmax)
                }
                if (lane < NTAG) {
                    d_bp[t * NTAG + lane] = (unsigned char)bi;
                    fv = best + fbase[j * NTAG + lane];
                }
            }
        }
        __syncthreads();
    }

    if (tid < 32) {
        float term = (lane < NTAG) ? (fv + __ldg(&trans[STOP_TAG * NTAG + lane])) : -3.4e38f;
        float best = -3.4e38f; int bi = 0;
#pragma unroll
        for (int p = 0; p < NTAG; p++) {
            float v = __shfl_sync(0xffffffffu, term, p);
            if (v > best) { best = v; bi = p; }
        }
        if (lane == 0) {
            d_best = bi;
            if (out_size > SEQ) out[0] = best;   // score at out[0] when layout has room
        }
    }
}

// ---------------- kernel 5: backtrace ----------------
#define BCH 1024
__global__ void k_backtrace(float* out, int out_size)
{
    __shared__ unsigned char bb[2][BCH * NTAG];
    int tid = threadIdx.x;
    const int nch = SEQ / BCH;
    if (tid >= 32) {   // preload last chunk
        const uint4* src = (const uint4*)&d_bp[(size_t)(nch - 1) * BCH * NTAG];
        uint4* dst = (uint4*)bb[(nch - 1) & 1];
        for (int i = tid - 32; i < BCH * NTAG / 16; i += (int)blockDim.x - 32) dst[i] = src[i];
    }
    __syncthreads();
    int off = (out_size > SEQ) ? (out_size - SEQ) : 0;
    int tag = d_best;
    for (int c = nch - 1; c >= 0; c--) {
        if (tid >= 32) {
            if (c > 0) {
                const uint4* src = (const uint4*)&d_bp[(size_t)(c - 1) * BCH * NTAG];
                uint4* dst = (uint4*)bb[(c - 1) & 1];
                for (int i = tid - 32; i < BCH * NTAG / 16; i += (int)blockDim.x - 32) dst[i] = src[i];
            }
        } else if (tid == 0) {
            const unsigned char* b = bb[c & 1];
            for (int j = BCH - 1; j >= 0; j--) {
                int s = c * BCH + j;
                out[off + s] = (float)tag;     // y[s] = tag entering step s's backpointer
                tag = b[j * NTAG + tag];       // carry = bp[s][tag]
            }
        }
        __syncthreads();
    }
}

// ---------------- launch ----------------
extern "C" void kernel_launch(void* const* d_in, const int* in_sizes, int n_in,
                              void* d_out, int out_size)
{
    const int*   sent  = (const int*)d_in[0];
    const float* embed = (const float*)d_in[1];
    const float* wihf  = (const float*)d_in[2];
    const float* whhf  = (const float*)d_in[3];
    const float* bihf  = (const float*)d_in[4];
    const float* bhhf  = (const float*)d_in[5];
    const float* wihb  = (const float*)d_in[6];
    const float* whhb  = (const float*)d_in[7];
    const float* bihb  = (const float*)d_in[8];
    const float* bhhb  = (const float*)d_in[9];
    const float* h0    = (const float*)d_in[10];
    const float* c0    = (const float*)d_in[11];
    const float* wtag  = (const float*)d_in[12];
    const float* btag  = (const float*)d_in[13];
    const float* trans = (const float*)d_in[14];
    float* out = (float*)d_out;

    cudaFuncSetAttribute(k_viterbi, cudaFuncAttributeMaxDynamicSharedMemorySize, VIT_SMEM_BYTES);

    // 1) embedding + input projections (8 tokens per block)
    k_embed_proj<<<SEQ / TOKB, TPB_E>>>(sent, embed, wihf, bihf, bhhf, wihb, bihb, bhhb);

    // 2) BiLSTM recurrence: 16 CTAs = 2 clusters of 8 (fwd / bwd), weights in registers
    {
        cudaLaunchConfig_t cfg = {};
        cfg.gridDim = dim3(16, 1, 1);
        cfg.blockDim = dim3(TPB_L, 1, 1);
        cfg.dynamicSmemBytes = 0;
        cfg.stream = 0;
        cudaLaunchAttribute attrs[1];
        attrs[0].id = cudaLaunchAttributeClusterDimension;
        attrs[0].val.clusterDim.x = 8;
        attrs[0].val.clusterDim.y = 1;
        attrs[0].val.clusterDim.z = 1;
        cfg.attrs = attrs;
        cfg.numAttrs = 1;
        cudaLaunchKernelEx(&cfg, k_lstm, whhf, whhb, h0, c0);
    }

    // 3) tag projection
    k_feats<<<SEQ, 640>>>(wtag, btag);

    // 4) Viterbi forward (single block: 1 compute warp + 7 loader warps)
    k_viterbi<<<1, 256, VIT_SMEM_BYTES>>>(trans, out, out_size);

    // 5) backtrace
    k_backtrace<<<1, 256>>>(out, out_size);
}